// round 16
// baseline (speedup 1.0000x reference)
#include <cuda_runtime.h>
#include <cuda_fp16.h>
#include <cstdint>

// Problem constants
#define TT 4096      // B*S tokens
#define HH 1024      // hidden
#define II 2048      // intermediate
#define EE 8         // experts

#define NSTAGE 4     // 4 stages + lead-2 prefetch => no trailing barrier needed
#define RS 40        // smem row stride in halves (80B; conflict-free for LDSM 8-row groups)

// ---------------- scratch (device globals: no allocation allowed) ----------
__device__ __half g_X[(size_t)TT * HH];          // fp16 x (8 MB)
__device__ __half g_F[(size_t)EE * TT * II];     // activations, expert-list order (128 MB)
__device__ __half g_W11T[(size_t)EE * II * HH];  // W11 transposed [e][i][h] fp16 (32 MB)
__device__ __half g_W12T[(size_t)EE * II * HH];  // W12 transposed [e][i][h] fp16 (32 MB)
__device__ __half g_W2T[(size_t)EE * HH * II];   // W2 transposed [e][h][i] fp16 (32 MB)
__device__ int    g_cnt[EE];
__device__ int    g_rows[EE * TT];               // stores r = t*2 + k
__device__ float  g_wts[EE * TT];

// ---------------- helpers ----------------
__device__ __forceinline__ void cp16(const void* smem_dst, const void* gmem_src) {
    unsigned s = (unsigned)__cvta_generic_to_shared(smem_dst);
    asm volatile("cp.async.cg.shared.global [%0], [%1], 16;\n" :: "r"(s), "l"(gmem_src));
}
#define CP_COMMIT() asm volatile("cp.async.commit_group;\n" ::: "memory")
#define CP_WAIT2()  asm volatile("cp.async.wait_group 2;\n" ::: "memory")

__device__ __forceinline__ void mma_f16(float c[4], const unsigned a[4], const unsigned b[2]) {
    asm volatile(
        "mma.sync.aligned.m16n8k16.row.col.f32.f16.f16.f32 "
        "{%0,%1,%2,%3}, {%4,%5,%6,%7}, {%8,%9}, {%0,%1,%2,%3};\n"
        : "+f"(c[0]), "+f"(c[1]), "+f"(c[2]), "+f"(c[3])
        : "r"(a[0]), "r"(a[1]), "r"(a[2]), "r"(a[3]), "r"(b[0]), "r"(b[1]));
}

__device__ __forceinline__ void ldsm4(unsigned r[4], const __half* p) {
    unsigned a = (unsigned)__cvta_generic_to_shared(p);
    asm volatile("ldmatrix.sync.aligned.m8n8.x4.shared.b16 {%0,%1,%2,%3}, [%4];"
                 : "=r"(r[0]), "=r"(r[1]), "=r"(r[2]), "=r"(r[3]) : "r"(a));
}

__device__ __forceinline__ void red_add_f32(float* p, float v) {
    asm volatile("red.global.add.f32 [%0], %1;" :: "l"(p), "f"(v) : "memory");
}

// ---------------- 0: zero expert counters (must precede prep's router) ----
__global__ void zero_cnt_kernel() {
    if (threadIdx.x < EE) g_cnt[threadIdx.x] = 0;
}

// ---------------- 1: fused prep: router + weight convert + zero_out -------
// 256 threads/block, 1D grid:
//   [0, 512)            router (8 warps = 8 tokens per block)
//   [512, 512+49152)    weight convert/transpose (64 x 32 x 24 flattened)
//   [+, +1024)          zero out (1M float4, 4 per thread)
#define PREP_ROUTER 512
#define PREP_CONV   49152
#define PREP_ZERO   1024
#define PREP_BLOCKS (PREP_ROUTER + PREP_CONV + PREP_ZERO)

__global__ __launch_bounds__(256) void prep_kernel(
    const float* __restrict__ x, const float* __restrict__ Wg,
    const float* __restrict__ W11, const float* __restrict__ W12,
    const float* __restrict__ W2, float* __restrict__ out)
{
    int b = blockIdx.x;
    int tid = threadIdx.x;

    if (b < PREP_ROUTER) {
        // ---- router: warp per token ----
        int t = b * 8 + (tid >> 5);
        int lane = tid & 31;
        const float* xr = x + (size_t)t * HH;
        __half* gx = g_X + (size_t)t * HH;
        float acc[EE];
#pragma unroll
        for (int e = 0; e < EE; e++) acc[e] = 0.f;
        for (int h = lane; h < HH; h += 32) {
            float xv = xr[h];
            gx[h] = __float2half_rn(xv);
            const float4* wg = reinterpret_cast<const float4*>(Wg + h * EE);
            float4 w0 = wg[0], w1 = wg[1];
            acc[0] += xv * w0.x; acc[1] += xv * w0.y; acc[2] += xv * w0.z; acc[3] += xv * w0.w;
            acc[4] += xv * w1.x; acc[5] += xv * w1.y; acc[6] += xv * w1.z; acc[7] += xv * w1.w;
        }
#pragma unroll
        for (int off = 16; off > 0; off >>= 1) {
#pragma unroll
            for (int e = 0; e < EE; e++)
                acc[e] += __shfl_xor_sync(0xffffffffu, acc[e], off);
        }
        if (lane == 0) {
            float m = acc[0];
#pragma unroll
            for (int e = 1; e < EE; e++) m = fmaxf(m, acc[e]);
            float p[EE];
            float s = 0.f;
#pragma unroll
            for (int e = 0; e < EE; e++) { p[e] = __expf(acc[e] - m); s += p[e]; }
            float inv = 1.f / s;
            int i0 = 0;
#pragma unroll
            for (int e = 1; e < EE; e++) if (p[e] > p[i0]) i0 = e;
            int i1 = -1;
#pragma unroll
            for (int e = 0; e < EE; e++) {
                if (e == i0) continue;
                if (i1 < 0 || p[e] > p[i1]) i1 = e;
            }
            float s0 = p[i0] * inv, s1 = p[i1] * inv;
            float denom = s0 + s1 + 1e-8f;
            float w0 = s0 / denom, w1 = s1 / denom;
            int pos0 = atomicAdd(&g_cnt[i0], 1);
            g_rows[i0 * TT + pos0] = t * 2 + 0;
            g_wts[i0 * TT + pos0] = w0;
            int pos1 = atomicAdd(&g_cnt[i1], 1);
            g_rows[i1 * TT + pos1] = t * 2 + 1;
            g_wts[i1 * TT + pos1] = w1;
        }
    } else if (b < PREP_ROUTER + PREP_CONV) {
        // ---- weight convert + transpose ----
        __shared__ float tile[32][33];
        int cidx = b - PREP_ROUTER;
        int bx = cidx & 63;
        int by = (cidx >> 6) & 31;
        int z = cidx >> 11;            // 0..23
        int sel = z / EE;
        int e = z % EE;
        int R, C;
        const float* src;
        __half* dstbase;
        if (sel == 0)      { R = HH; C = II; src = W11; dstbase = g_W11T; }
        else if (sel == 1) { R = HH; C = II; src = W12; dstbase = g_W12T; }
        else               { R = II; C = HH; src = W2;  dstbase = g_W2T;
                             int tswap = bx; bx = by; by = tswap; }
        int c0 = bx * 32, r0 = by * 32;
        int tx = tid & 31, ty = tid >> 5;
        const float* s = src + (size_t)e * R * C;
#pragma unroll
        for (int j = 0; j < 4; j++)
            tile[ty + 8 * j][tx] = s[(size_t)(r0 + ty + 8 * j) * C + c0 + tx];
        __syncthreads();
        __half* d = dstbase + (size_t)e * R * C;
        int pr = tid & 15, cr = tid >> 4;
#pragma unroll
        for (int j2 = 0; j2 < 2; j2++) {
            int c = cr + 16 * j2;
            __half2 v = __floats2half2_rn(tile[2 * pr][c], tile[2 * pr + 1][c]);
            *reinterpret_cast<__half2*>(d + (size_t)(c0 + c) * R + r0 + 2 * pr) = v;
        }
    } else {
        // ---- zero output (RED target): 1024 float4 per block ----
        int zb = b - PREP_ROUTER - PREP_CONV;
        float4* o4 = reinterpret_cast<float4*>(out);
#pragma unroll
        for (int j = 0; j < 4; j++)
            o4[zb * 1024 + j * 256 + tid] = make_float4(0.f, 0.f, 0.f, 0.f);
    }
}

// smem sizing (halves)
#define G1_A_H   (64 * RS)
#define G1_B_H   (128 * RS)
#define G1_SMEM_B  ((NSTAGE * (G1_A_H + 2 * G1_B_H)) * 2)   // 102400 B
#define G2_A_H   (128 * RS)
#define G2_B_H   (128 * RS)
#define G2_SMEM_B  ((NSTAGE * (G2_A_H + G2_B_H)) * 2)       // 81920 B

// ---------------- 2: grouped GEMM1: F = SiLU(X@W11) * (X@W12) -------------
// fp16 m16n8k16 + ldmatrix. 256 threads. BM=64, BN=128, BK=32.
// Writes g_F in expert-list order (e*TT + list position) -> gemm2 A is sequential.
// grid: (II/128, TT/64, EE)
__global__ __launch_bounds__(256, 2) void gemm1_kernel()
{
    extern __shared__ __half dynh[];
    int e = blockIdx.z;
    int cnt = g_cnt[e];
    int m0 = blockIdx.y * 64;
    if (m0 >= cnt) return;
    int n0 = blockIdx.x * 128;

    __half* AsB  = dynh;                          // [NSTAGE][64][RS]
    __half* B1sB = dynh + NSTAGE * G1_A_H;        // [NSTAGE][128][RS]
    __half* B2sB = B1sB + NSTAGE * G1_B_H;        // [NSTAGE][128][RS]
    __shared__ int rloc[64];

    int tid = threadIdx.x;
    int lane = tid & 31;
    int warp = tid >> 5;
    int gid = lane >> 2;
    int tig = lane & 3;
    int wm = (warp >> 2) * 32;
    int wn = (warp & 3) * 32;

    int a_lrow = (lane & 7) + ((lane >> 3) & 1) * 8;
    int a_lk   = (lane >> 4) * 8;
    int b_lrow = (lane & 7) + ((lane >> 4) & 1) * 8;
    int b_lk   = ((lane >> 3) & 1) * 8;

    if (tid < 64) {
        int mi = m0 + tid;
        if (mi >= cnt) mi = cnt - 1;
        rloc[tid] = g_rows[e * TT + mi];
    }
    __syncthreads();

    int a_row = tid >> 2, a_ch = (tid & 3) * 8;
    const __half* a_src = g_X + (size_t)(rloc[a_row] >> 1) * HH + a_ch;
    const __half* b1_src[2];
    const __half* b2_src[2];
    int b_soff[2];
#pragma unroll
    for (int p = 0; p < 2; p++) {
        int idx = tid + p * 256;
        int row = idx >> 2;
        int ch = (idx & 3) * 8;
        b1_src[p] = g_W11T + ((size_t)e * II + n0 + row) * HH + ch;
        b2_src[p] = g_W12T + ((size_t)e * II + n0 + row) * HH + ch;
        b_soff[p] = row * RS + ch;
    }
    int a_soff = a_row * RS + a_ch;

    float cG[2][4][4], cV[2][4][4];
#pragma unroll
    for (int a = 0; a < 2; a++)
#pragma unroll
        for (int b = 0; b < 4; b++)
#pragma unroll
            for (int c = 0; c < 4; c++) { cG[a][b][c] = 0.f; cV[a][b][c] = 0.f; }

    const int NIT = HH / 32;   // 32

#pragma unroll
    for (int pre = 0; pre < 2; pre++) {
        int kk = pre * 32;
        __half* As = AsB + pre * G1_A_H;
        __half* B1 = B1sB + pre * G1_B_H;
        __half* B2 = B2sB + pre * G1_B_H;
        cp16(As + a_soff, a_src + kk);
#pragma unroll
        for (int p = 0; p < 2; p++) {
            cp16(B1 + b_soff[p], b1_src[p] + kk);
            cp16(B2 + b_soff[p], b2_src[p] + kk);
        }
        CP_COMMIT();
    }

    int buf = 0;
    for (int it = 0; it < NIT; it++) {
        if (it + 2 < NIT) {
            int kk = (it + 2) * 32;
            int s = (it + 2) & (NSTAGE - 1);
            __half* As = AsB + s * G1_A_H;
            __half* B1 = B1sB + s * G1_B_H;
            __half* B2 = B2sB + s * G1_B_H;
            cp16(As + a_soff, a_src + kk);
#pragma unroll
            for (int p = 0; p < 2; p++) {
                cp16(B1 + b_soff[p], b1_src[p] + kk);
                cp16(B2 + b_soff[p], b2_src[p] + kk);
            }
        }
        CP_COMMIT();
        CP_WAIT2();
        __syncthreads();

        const __half* Abuf  = AsB + buf * G1_A_H;
        const __half* B1buf = B1sB + buf * G1_B_H;
        const __half* B2buf = B2sB + buf * G1_B_H;

#pragma unroll
        for (int ks = 0; ks < 2; ks++) {
            unsigned a[2][4];
#pragma unroll
            for (int mt = 0; mt < 2; mt++)
                ldsm4(a[mt], Abuf + (wm + mt * 16 + a_lrow) * RS + ks * 16 + a_lk);
#pragma unroll
            for (int np = 0; np < 2; np++) {
                unsigned b1[4], b2[4];
                ldsm4(b1, B1buf + (wn + np * 16 + b_lrow) * RS + ks * 16 + b_lk);
                ldsm4(b2, B2buf + (wn + np * 16 + b_lrow) * RS + ks * 16 + b_lk);
#pragma unroll
                for (int h = 0; h < 2; h++) {
                    unsigned bb1[2] = { b1[2 * h], b1[2 * h + 1] };
                    unsigned bb2[2] = { b2[2 * h], b2[2 * h + 1] };
#pragma unroll
                    for (int mt = 0; mt < 2; mt++) {
                        mma_f16(cG[mt][np * 2 + h], a[mt], bb1);
                        mma_f16(cV[mt][np * 2 + h], a[mt], bb2);
                    }
                }
            }
        }
        buf++; if (buf == NSTAGE) buf = 0;
    }

    // epilogue: f = g * sigmoid(g) * v -> g_F[e*TT + list position] (fp16)
#pragma unroll
    for (int mt = 0; mt < 2; mt++) {
#pragma unroll
        for (int half = 0; half < 2; half++) {
            int r = wm + mt * 16 + gid + half * 8;
            if (m0 + r < cnt) {
                __half* dst = g_F + ((size_t)e * TT + m0 + r) * II + n0 + wn;
#pragma unroll
                for (int nt = 0; nt < 4; nt++) {
                    float g0 = cG[mt][nt][half * 2 + 0], g1 = cG[mt][nt][half * 2 + 1];
                    float v0 = cV[mt][nt][half * 2 + 0], v1 = cV[mt][nt][half * 2 + 1];
                    float f0 = g0 * v0 / (1.f + __expf(-g0));
                    float f1 = g1 * v1 / (1.f + __expf(-g1));
                    *reinterpret_cast<__half2*>(dst + nt * 8 + tig * 2) =
                        __floats2half2_rn(f0, f1);
                }
            }
        }
    }
}

// ---------------- 3: grouped GEMM2: out += w[r] * (F[r] @ W2[e]) ----------
// fp16 m16n8k16 + ldmatrix. 256 threads. BM=128, BN=128, BK=32.
// A (g_F) now sequential in expert-list order. RED epilogue into out.
// grid: (HH/128, TT/128, EE)
__global__ __launch_bounds__(256, 2) void gemm2_kernel(float* __restrict__ out)
{
    extern __shared__ __half dynh[];
    int e = blockIdx.z;
    int cnt = g_cnt[e];
    int m0 = blockIdx.y * 128;
    if (m0 >= cnt) return;
    int n0 = blockIdx.x * 128;

    __half* AsB = dynh;                           // [NSTAGE][128][RS]
    __half* BsB = dynh + NSTAGE * G2_A_H;         // [NSTAGE][128][RS]
    __shared__ int rloc[128];
    __shared__ float wloc[128];

    int tid = threadIdx.x;
    int lane = tid & 31;
    int warp = tid >> 5;
    int gid = lane >> 2;
    int tig = lane & 3;
    int wm = (warp >> 2) * 64;
    int wn = (warp & 3) * 32;

    int a_lrow = (lane & 7) + ((lane >> 3) & 1) * 8;
    int a_lk   = (lane >> 4) * 8;
    int b_lrow = (lane & 7) + ((lane >> 4) & 1) * 8;
    int b_lk   = ((lane >> 3) & 1) * 8;

    if (tid < 128) {
        int mi = m0 + tid;
        if (mi >= cnt) mi = cnt - 1;
        rloc[tid] = g_rows[e * TT + mi];
        wloc[tid] = g_wts[e * TT + mi];
    }
    __syncthreads();

    const __half* a_src[2];
    const __half* b_src[2];
    int soff[2];
#pragma unroll
    for (int p = 0; p < 2; p++) {
        int idx = tid + p * 256;
        int row = idx >> 2;
        int ch = (idx & 3) * 8;
        a_src[p] = g_F + ((size_t)e * TT + m0 + row) * II + ch;   // sequential rows
        b_src[p] = g_W2T + ((size_t)e * HH + n0 + row) * II + ch;
        soff[p] = row * RS + ch;
    }

    float c[4][4][4];
#pragma unroll
    for (int a = 0; a < 4; a++)
#pragma unroll
        for (int b = 0; b < 4; b++)
#pragma unroll
            for (int cc = 0; cc < 4; cc++) c[a][b][cc] = 0.f;

    const int NIT = II / 32;   // 64

#pragma unroll
    for (int pre = 0; pre < 2; pre++) {
        int kk = pre * 32;
        __half* As = AsB + pre * G2_A_H;
        __half* Bs = BsB + pre * G2_B_H;
#pragma unroll
        for (int p = 0; p < 2; p++) {
            cp16(As + soff[p], a_src[p] + kk);
            cp16(Bs + soff[p], b_src[p] + kk);
        }
        CP_COMMIT();
    }

    int buf = 0;
    for (int it = 0; it < NIT; it++) {
        if (it + 2 < NIT) {
            int kk = (it + 2) * 32;
            int s = (it + 2) & (NSTAGE - 1);
            __half* As = AsB + s * G2_A_H;
            __half* Bs = BsB + s * G2_B_H;
#pragma unroll
            for (int p = 0; p < 2; p++) {
                cp16(As + soff[p], a_src[p] + kk);
                cp16(Bs + soff[p], b_src[p] + kk);
            }
        }
        CP_COMMIT();
        CP_WAIT2();
        __syncthreads();

        const __half* Abuf = AsB + buf * G2_A_H;
        const __half* Bbuf = BsB + buf * G2_B_H;

#pragma unroll
        for (int ks = 0; ks < 2; ks++) {
            unsigned a[4][4];
#pragma unroll
            for (int mt = 0; mt < 4; mt++)
                ldsm4(a[mt], Abuf + (wm + mt * 16 + a_lrow) * RS + ks * 16 + a_lk);
#pragma unroll
            for (int np = 0; np < 2; np++) {
                unsigned b[4];
                ldsm4(b, Bbuf + (wn + np * 16 + b_lrow) * RS + ks * 16 + b_lk);
#pragma unroll
                for (int h = 0; h < 2; h++) {
                    unsigned bb[2] = { b[2 * h], b[2 * h + 1] };
#pragma unroll
                    for (int mt = 0; mt < 4; mt++)
                        mma_f16(c[mt][np * 2 + h], a[mt], bb);
                }
            }
        }
        buf++; if (buf == NSTAGE) buf = 0;
    }

    // epilogue: scale by routing weight, RED into out[token]
#pragma unroll
    for (int mt = 0; mt < 4; mt++) {
#pragma unroll
        for (int half = 0; half < 2; half++) {
            int r = wm + mt * 16 + gid + half * 8;
            if (m0 + r < cnt) {
                int tok = rloc[r] >> 1;
                float wr = wloc[r];
                float* dst = out + (size_t)tok * HH + n0 + wn;
#pragma unroll
                for (int nt = 0; nt < 4; nt++) {
                    red_add_f32(dst + nt * 8 + tig * 2 + 0, wr * c[mt][nt][half * 2 + 0]);
                    red_add_f32(dst + nt * 8 + tig * 2 + 1, wr * c[mt][nt][half * 2 + 1]);
                }
            }
        }
    }
}

// ---------------- launch ----------------
extern "C" void kernel_launch(void* const* d_in, const int* in_sizes, int n_in,
                              void* d_out, int out_size) {
    (void)in_sizes; (void)n_in; (void)out_size;
    const float* x   = (const float*)d_in[0];
    const float* Wg  = (const float*)d_in[1];
    const float* W11 = (const float*)d_in[2];
    const float* W12 = (const float*)d_in[3];
    const float* W2  = (const float*)d_in[4];
    float* out = (float*)d_out;

    cudaFuncSetAttribute(gemm1_kernel, cudaFuncAttributeMaxDynamicSharedMemorySize, G1_SMEM_B);
    cudaFuncSetAttribute(gemm2_kernel, cudaFuncAttributeMaxDynamicSharedMemorySize, G2_SMEM_B);

    zero_cnt_kernel<<<1, 32>>>();
    prep_kernel<<<PREP_BLOCKS, 256>>>(x, Wg, W11, W12, W2, out);

    dim3 g1(II / 128, TT / 64, EE);                        // (16, 64, 8)
    gemm1_kernel<<<g1, 256, G1_SMEM_B>>>();

    dim3 g2(HH / 128, TT / 128, EE);                       // (8, 32, 8)
    gemm2_kernel<<<g2, 256, G2_SMEM_B>>>(out);
}